// round 2
// baseline (speedup 1.0000x reference)
#include <cuda_runtime.h>
#include <cuda_fp16.h>
#include <math.h>

// B=64, I=2048, N=16 (in_dim), J=16 (num_caps), M=16 (dim), 3 routing iters
#define B_  64
#define I_  2048
#define N_  16
#define J_  16
#define M_  16
#define JM  256
#define CHUNKS 16
#define WPC 8
#define IW (I_/(CHUNKS*WPC))   // 16 input capsules per warp per pass

// Scratch (device globals; fp16 u_hat = 67 MB -> fits L2)
__device__ __half g_uhat[(size_t)B_ * I_ * JM];   // [b][i][j*16+m]
__device__ float  g_s[B_ * JM];
__device__ float  g_osum[B_ * JM];
__device__ int    g_cnt[B_];

// ---- packed f32x2 helpers (Blackwell FFMA2) --------------------------------
__device__ __forceinline__ unsigned long long pack2(float lo, float hi) {
    unsigned long long r;
    asm("mov.b64 %0, {%1, %2};" : "=l"(r) : "f"(lo), "f"(hi));
    return r;
}
__device__ __forceinline__ void unpack2(unsigned long long v, float& lo, float& hi) {
    asm("mov.b64 {%0, %1}, %2;" : "=f"(lo), "=f"(hi) : "l"(v));
}
__device__ __forceinline__ void fma2(unsigned long long& acc,
                                     unsigned long long a, unsigned long long b) {
    asm("fma.rn.f32x2 %0, %1, %2, %3;" : "=l"(acc) : "l"(a), "l"(b), "l"(acc));
}

// ---------------------------------------------------------------------------
// K1: u_hat[b,i,j,m] = sum_n inputs[b,i,n] * W[i,j,n,m]   (stored fp16)
// grid = I_ (CTA per i), block 256 (thread = j*16+m). Two b's per FFMA2.
// Side job: CTAs 0..63 zero the small accumulators + counters.
__global__ void __launch_bounds__(256) k_uhat(const float* __restrict__ inp,
                                              const float* __restrict__ W) {
    const int i = blockIdx.x;
    const int t = threadIdx.x;

    if (blockIdx.x < B_) {
        g_s[blockIdx.x * JM + t]    = 0.f;
        g_osum[blockIdx.x * JM + t] = 0.f;
        if (t == 0) g_cnt[blockIdx.x] = 0;
    }

    __shared__ float  Ws[J_ * N_ * M_];          // 16 KB: W[i][j][n][m]
    __shared__ float2 Xs[(B_ / 2) * N_];         // 4 KB: Xs[bp][n]={x[2bp][n],x[2bp+1][n]}

    const float* Wp = W + (size_t)i * (J_ * N_ * M_);
    #pragma unroll
    for (int k = t; k < J_ * N_ * M_; k += 256) Ws[k] = Wp[k];
    for (int k = t; k < B_ * N_; k += 256) {
        int b = k >> 4, n = k & 15;
        ((float*)&Xs[(b >> 1) * N_ + n])[b & 1] = inp[((size_t)b * I_ + i) * N_ + n];
    }
    __syncthreads();

    const int j = t >> 4, m = t & 15;
    unsigned long long w2[N_];
    #pragma unroll
    for (int n = 0; n < N_; n++) {
        float w = Ws[j * (N_ * M_) + n * M_ + m];
        w2[n] = pack2(w, w);
    }

    __half* up = g_uhat + (size_t)i * JM + t;    // +b*I_*JM per batch row
    #pragma unroll 2
    for (int bp = 0; bp < B_ / 2; bp++) {
        const ulonglong2* X22 = (const ulonglong2*)(Xs + bp * N_);  // 8 x LDS.128
        unsigned long long acc = 0ull;                              // {0.f, 0.f}
        #pragma unroll
        for (int q = 0; q < 8; q++) {
            ulonglong2 z = X22[q];
            fma2(acc, z.x, w2[2 * q]);
            fma2(acc, z.y, w2[2 * q + 1]);
        }
        float a0, a1; unpack2(acc, a0, a1);
        up[(size_t)(2 * bp)     * I_ * JM] = __float2half_rn(a0);
        up[(size_t)(2 * bp + 1) * I_ * JM] = __float2half_rn(a1);
    }
}

// ---------------------------------------------------------------------------
// K2: one routing pass + fused squash (last CTA per b).
//   logits[b,i,j] = dot_m(osum[b,j,:], u_hat[b,i,j,:])
//   c = softmax_j(logits);  s[b,j,m] = sum_i c * u_hat[b,i,j,m]
//   outputs = squash(s); osum += outputs (or write d_out on final pass)
// grid = (B_, CHUNKS), block 256. Lane l owns (j=l/2, m in [(l&1)*8, +8)).
__global__ void __launch_bounds__(256) k_route(float* __restrict__ out, int final_pass) {
    const int b     = blockIdx.x;
    const int chunk = blockIdx.y;
    const int wid   = threadIdx.x >> 5;
    const int lane  = threadIdx.x & 31;

    __shared__ float os[JM];
    __shared__ float ss[JM];
    os[threadIdx.x] = g_osum[b * JM + threadIdx.x];
    ss[threadIdx.x] = 0.f;
    __syncthreads();

    const int j = lane >> 1, mbase = (lane & 1) * 8;
    float o[8];
    #pragma unroll
    for (int k = 0; k < 8; k++) o[k] = os[j * M_ + mbase + k];

    float acc[8];
    #pragma unroll
    for (int k = 0; k < 8; k++) acc[k] = 0.f;

    const int i0 = (chunk * WPC + wid) * IW;
    const int4* base = (const int4*)(g_uhat + ((size_t)b * I_ + i0) * JM);

    #pragma unroll 4
    for (int ii = 0; ii < IW; ii++) {
        int4 v = base[ii * (JM / 8) + lane];    // 16B = 8 halves, coalesced 512B/warp
        float u[8];
        const __half2* hp = (const __half2*)&v;
        #pragma unroll
        for (int q = 0; q < 4; q++) {
            float2 f = __half22float2(hp[q]);
            u[2 * q] = f.x; u[2 * q + 1] = f.y;
        }
        float p = u[0]*o[0] + u[1]*o[1] + u[2]*o[2] + u[3]*o[3]
                + u[4]*o[4] + u[5]*o[5] + u[6]*o[6] + u[7]*o[7];
        p += __shfl_xor_sync(0xffffffffu, p, 1);        // full logit[j]

        float mx = p;
        #pragma unroll
        for (int off = 2; off < 32; off <<= 1)
            mx = fmaxf(mx, __shfl_xor_sync(0xffffffffu, mx, off));
        float e = __expf(p - mx);
        float sum = e;
        #pragma unroll
        for (int off = 2; off < 32; off <<= 1)
            sum += __shfl_xor_sync(0xffffffffu, sum, off);
        float c = e / sum;

        #pragma unroll
        for (int k = 0; k < 8; k++) acc[k] += c * u[k];
    }

    float* sp = ss + j * M_ + mbase;
    #pragma unroll
    for (int k = 0; k < 8; k++) atomicAdd(sp + k, acc[k]);
    __syncthreads();
    atomicAdd(&g_s[b * JM + threadIdx.x], ss[threadIdx.x]);

    // -------- fused squash: last CTA of this b finishes the pass ----------
    __threadfence();
    __shared__ int isLast;
    if (threadIdx.x == 0) {
        int prev = atomicAdd(&g_cnt[b], 1);
        isLast = (prev == (int)gridDim.y - 1);
    }
    __syncthreads();
    if (!isLast) return;
    __threadfence();

    float s = *((volatile float*)&g_s[b * JM + threadIdx.x]);
    float n2 = s * s;
    #pragma unroll
    for (int off = 1; off < 16; off <<= 1)          // reduce over m
        n2 += __shfl_xor_sync(0xffffffffu, n2, off);
    float v = n2 / (1.f + n2) * rsqrtf(n2 + 1e-8f) * s;

    if (final_pass) {
        out[b * JM + threadIdx.x] = v;
    } else {
        g_osum[b * JM + threadIdx.x] += v;
        g_s[b * JM + threadIdx.x] = 0.f;
    }
    if (threadIdx.x == 0) g_cnt[b] = 0;
}

// ---------------------------------------------------------------------------
extern "C" void kernel_launch(void* const* d_in, const int* in_sizes, int n_in,
                              void* d_out, int out_size) {
    const float* inp = (const float*)d_in[0];   // [B, I, N]
    const float* W   = (const float*)d_in[1];   // [I, J, N, M]
    float* out = (float*)d_out;                 // [B, J, M]

    dim3 rgrid(B_, CHUNKS);
    k_uhat<<<I_, 256>>>(inp, W);
    k_route<<<rgrid, 256>>>(out, 0);   // iter 0 (osum=0 -> uniform softmax)
    k_route<<<rgrid, 256>>>(out, 0);   // iter 1
    k_route<<<rgrid, 256>>>(out, 1);   // iter 2 -> d_out
}

// round 3
// speedup vs baseline: 1.8283x; 1.8283x over previous
#include <cuda_runtime.h>
#include <cuda_fp16.h>
#include <math.h>

// B=64, I=2048, N=16, J=16, M=16, 3 routing iters
#define B_  64
#define I_  2048
#define N_  16
#define J_  16
#define M_  16
#define JM  256
#define CHUNKS 16
#define WPC 8
#define IW (I_/(CHUNKS*WPC))   // 16 i per warp per route pass

// Scratch (device globals). fp16 u_hat = 67 MB -> L2 resident.
__device__ __half g_uhat[(size_t)B_ * I_ * JM];     // [b][i][j*16+m]
__device__ float  g_scratch[3 * B_ * JM];           // s0 | s1 | s2
__device__ float  g_osum[B_ * JM];
__device__ int    g_counters[3 * B_];

// ---- packed f32x2 helpers --------------------------------------------------
__device__ __forceinline__ unsigned long long pack2(float lo, float hi) {
    unsigned long long r;
    asm("mov.b64 %0, {%1, %2};" : "=l"(r) : "f"(lo), "f"(hi));
    return r;
}
__device__ __forceinline__ void unpack2(unsigned long long v, float& lo, float& hi) {
    asm("mov.b64 {%0, %1}, %2;" : "=f"(lo), "=f"(hi) : "l"(v));
}
__device__ __forceinline__ void fma2(unsigned long long& acc,
                                     unsigned long long a, unsigned long long b) {
    asm("fma.rn.f32x2 %0, %1, %2, %3;" : "=l"(acc) : "l"(a), "l"(b), "l"(acc));
}

// ---------------------------------------------------------------------------
// K1: u_hat[b,i,j,m] = sum_n inputs[b,i,n] * W[i,j,n,m]   (stored fp16)
__global__ void __launch_bounds__(256) k_uhat(const float* __restrict__ inp,
                                              const float* __restrict__ W) {
    const int i = blockIdx.x;
    const int t = threadIdx.x;
    __shared__ float  Ws[J_ * N_ * M_];
    __shared__ float2 Xs[(B_ / 2) * N_];

    const float* Wp = W + (size_t)i * (J_ * N_ * M_);
    #pragma unroll
    for (int k = t; k < J_ * N_ * M_; k += 256) Ws[k] = Wp[k];
    for (int k = t; k < B_ * N_; k += 256) {
        int b = k >> 4, n = k & 15;
        ((float*)&Xs[(b >> 1) * N_ + n])[b & 1] = inp[((size_t)b * I_ + i) * N_ + n];
    }
    __syncthreads();

    const int j = t >> 4, m = t & 15;
    unsigned long long w2[N_];
    #pragma unroll
    for (int n = 0; n < N_; n++) {
        float w = Ws[j * (N_ * M_) + n * M_ + m];
        w2[n] = pack2(w, w);
    }

    __half* up = g_uhat + (size_t)i * JM + t;
    #pragma unroll 2
    for (int bp = 0; bp < B_ / 2; bp++) {
        const ulonglong2* X22 = (const ulonglong2*)(Xs + bp * N_);
        unsigned long long acc = 0ull;
        #pragma unroll
        for (int q = 0; q < 8; q++) {
            ulonglong2 z = X22[q];
            fma2(acc, z.x, w2[2 * q]);
            fma2(acc, z.y, w2[2 * q + 1]);
        }
        float a0, a1; unpack2(acc, a0, a1);
        up[(size_t)(2 * bp)     * I_ * JM] = __float2half_rn(a0);
        up[(size_t)(2 * bp + 1) * I_ * JM] = __float2half_rn(a1);
    }
}

// ---------------------------------------------------------------------------
// shared squash-update epilogue: last CTA of batch b finalizes the pass
__device__ __forceinline__ void squash_epilogue(int b, float* s_acc, int* cnt,
                                                float pre_scale, int final_pass,
                                                float* out, int ny) {
    __threadfence();
    __shared__ int isLast;
    if (threadIdx.x == 0)
        isLast = (atomicAdd(&cnt[b], 1) == ny - 1);
    __syncthreads();
    if (!isLast) return;
    __threadfence();

    float s = *((volatile float*)&s_acc[b * JM + threadIdx.x]) * pre_scale;
    float n2 = s * s;
    #pragma unroll
    for (int off = 1; off < 16; off <<= 1)
        n2 += __shfl_xor_sync(0xffffffffu, n2, off);
    float v = n2 / (1.f + n2) * rsqrtf(n2 + 1e-8f) * s;

    if (final_pass) out[b * JM + threadIdx.x] = v;
    else            atomicAdd(&g_osum[b * JM + threadIdx.x], v);  // osum += v
}

// ---------------------------------------------------------------------------
// K2: iteration 0 = pure reduction: s0[b,t] = sum_i u_hat[b,i,t]; v0=squash(s0/16)
// grid (B_, 16), 256 thr. Warp w handles 16 i's; lane reads int4 (8 halves).
__global__ void __launch_bounds__(256) k_red0() {
    const int b    = blockIdx.x;
    const int wid  = threadIdx.x >> 5;
    const int lane = threadIdx.x & 31;

    __shared__ float ss[JM];
    ss[threadIdx.x] = 0.f;
    __syncthreads();

    const int i0 = blockIdx.y * 128 + wid * 16;
    const int4* base = (const int4*)(g_uhat + ((size_t)b * I_ + i0) * JM);

    float acc[8];
    #pragma unroll
    for (int k = 0; k < 8; k++) acc[k] = 0.f;
    #pragma unroll 4
    for (int ii = 0; ii < 16; ii++) {
        int4 v = base[ii * (JM / 8) + lane];
        const __half2* hp = (const __half2*)&v;
        #pragma unroll
        for (int q = 0; q < 4; q++) {
            float2 f = __half22float2(hp[q]);
            acc[2 * q] += f.x; acc[2 * q + 1] += f.y;
        }
    }
    float* sp = ss + lane * 8;
    #pragma unroll
    for (int k = 0; k < 8; k++) atomicAdd(sp + k, acc[k]);
    __syncthreads();
    atomicAdd(&g_scratch[b * JM + threadIdx.x], ss[threadIdx.x]);

    squash_epilogue(b, g_scratch, g_counters, 1.f / 16.f, 0, nullptr, gridDim.y);
}

// ---------------------------------------------------------------------------
// K3: routing pass (iters 1,2) with 8-wide batched softmax.
// grid (B_, CHUNKS), 256 thr. Lane l owns (j=l>>1, m in [(l&1)*8,+8)).
__global__ void __launch_bounds__(256) k_route(float* __restrict__ s_acc,
                                               int* __restrict__ cnt,
                                               float* __restrict__ out,
                                               int final_pass) {
    const int b    = blockIdx.x;
    const int wid  = threadIdx.x >> 5;
    const int lane = threadIdx.x & 31;

    __shared__ float os[JM];
    __shared__ float ss[JM];
    os[threadIdx.x] = g_osum[b * JM + threadIdx.x];
    ss[threadIdx.x] = 0.f;
    __syncthreads();

    float o[8];
    #pragma unroll
    for (int k = 0; k < 8; k++) o[k] = os[lane * 8 + k];

    float acc[8];
    #pragma unroll
    for (int k = 0; k < 8; k++) acc[k] = 0.f;

    const int i0 = (blockIdx.y * WPC + wid) * IW;
    const int4* base = (const int4*)(g_uhat + ((size_t)b * I_ + i0) * JM);

    #pragma unroll
    for (int batch = 0; batch < IW / 8; batch++) {
        int4 v[8];
        #pragma unroll
        for (int r = 0; r < 8; r++)
            v[r] = base[(batch * 8 + r) * (JM / 8) + lane];

        float p[8];
        #pragma unroll
        for (int r = 0; r < 8; r++) {
            const __half2* hp = (const __half2*)&v[r];
            float2 f0 = __half22float2(hp[0]), f1 = __half22float2(hp[1]);
            float2 f2 = __half22float2(hp[2]), f3 = __half22float2(hp[3]);
            p[r] = f0.x*o[0] + f0.y*o[1] + f1.x*o[2] + f1.y*o[3]
                 + f2.x*o[4] + f2.y*o[5] + f3.x*o[6] + f3.y*o[7];
        }
        #pragma unroll
        for (int r = 0; r < 8; r++) p[r] += __shfl_xor_sync(0xffffffffu, p[r], 1);
        #pragma unroll
        for (int r = 0; r < 8; r++) p[r] = __expf(p[r]);   // no max-sub: bounded
        float sum[8];
        #pragma unroll
        for (int r = 0; r < 8; r++) sum[r] = p[r];
        #pragma unroll
        for (int off = 2; off < 32; off <<= 1) {
            #pragma unroll
            for (int r = 0; r < 8; r++)
                sum[r] += __shfl_xor_sync(0xffffffffu, sum[r], off);
        }
        #pragma unroll
        for (int r = 0; r < 8; r++) {
            float c = __fdividef(p[r], sum[r]);
            const __half2* hp = (const __half2*)&v[r];
            float2 f0 = __half22float2(hp[0]), f1 = __half22float2(hp[1]);
            float2 f2 = __half22float2(hp[2]), f3 = __half22float2(hp[3]);
            acc[0] += c * f0.x; acc[1] += c * f0.y;
            acc[2] += c * f1.x; acc[3] += c * f1.y;
            acc[4] += c * f2.x; acc[5] += c * f2.y;
            acc[6] += c * f3.x; acc[7] += c * f3.y;
        }
    }

    float* sp = ss + lane * 8;
    #pragma unroll
    for (int k = 0; k < 8; k++) atomicAdd(sp + k, acc[k]);
    __syncthreads();
    atomicAdd(&s_acc[b * JM + threadIdx.x], ss[threadIdx.x]);

    squash_epilogue(b, s_acc, cnt, 1.f, final_pass, out, gridDim.y);
}

// ---------------------------------------------------------------------------
extern "C" void kernel_launch(void* const* d_in, const int* in_sizes, int n_in,
                              void* d_out, int out_size) {
    const float* inp = (const float*)d_in[0];   // [B, I, N]
    const float* W   = (const float*)d_in[1];   // [I, J, N, M]
    float* out = (float*)d_out;                 // [B, J, M]

    void *p_scr, *p_cnt, *p_os;
    cudaGetSymbolAddress(&p_scr, g_scratch);
    cudaGetSymbolAddress(&p_cnt, g_counters);
    cudaGetSymbolAddress(&p_os,  g_osum);
    cudaMemsetAsync(p_scr, 0, 3 * B_ * JM * sizeof(float));
    cudaMemsetAsync(p_cnt, 0, 3 * B_ * sizeof(int));
    cudaMemsetAsync(p_os,  0, B_ * JM * sizeof(float));

    float* s1 = (float*)p_scr + B_ * JM;
    float* s2 = (float*)p_scr + 2 * B_ * JM;
    int* c1 = (int*)p_cnt + B_;
    int* c2 = (int*)p_cnt + 2 * B_;

    dim3 rg(B_, CHUNKS);
    k_uhat<<<I_, 256>>>(inp, W);
    k_red0<<<dim3(B_, 16), 256>>>();            // iter 0 (uniform c) + squash
    k_route<<<rg, 256>>>(s1, c1, out, 0);       // iter 1
    k_route<<<rg, 256>>>(s2, c2, out, 1);       // iter 2 -> d_out
}